// round 9
// baseline (speedup 1.0000x reference)
#include <cuda_runtime.h>
#include <cstdint>

#define TOK    16384
#define DIM    2048
#define NE     16
#define BT     64
#define NTHR   256
#define NCHUNK 32            // K chunks of 64

// stage: x[st0..7][tok0..63][8f] = 16384 B ; W[st][e0..15][8f] = 4096 B
#define XSTAGE_B 16384u
#define STAGE_B  20480u
#define SMEM_BYTES (4 * 20480)   // 81920 ; logits reuse stage 0

__device__ __forceinline__ uint32_t smem_u32(const void* p) {
    uint32_t a;
    asm("{ .reg .u64 t; cvta.to.shared.u64 t, %1; cvt.u32.u64 %0, t; }" : "=r"(a) : "l"(p));
    return a;
}

#define CP_ASYNC16(saddr, gptr) \
    asm volatile("cp.async.cg.shared.global [%0], [%1], 16;" :: "r"(saddr), "l"(gptr))
#define CP_COMMIT() asm volatile("cp.async.commit_group;" ::: "memory")
#define CP_WAIT2()  asm volatile("cp.async.wait_group 2;" ::: "memory")
#define CP_WAIT1()  asm volatile("cp.async.wait_group 1;" ::: "memory")
#define CP_WAIT0()  asm volatile("cp.async.wait_group 0;" ::: "memory")

#define LDS64(a, b, addr) \
    asm volatile("ld.shared.v2.f32 {%0, %1}, [%2];" : "=f"(a), "=f"(b) : "r"(addr))
#define STS64(addr, a, b) \
    asm volatile("st.shared.v2.f32 [%0], {%1, %2};" :: "r"(addr), "f"(a), "f"(b))
#define LDS32(v, addr) asm volatile("ld.shared.f32 %0, [%1];" : "=f"(v) : "r"(addr))
#define CVT_TF32(h, v) asm("cvt.rna.tf32.f32 %0, %1;" : "=r"(h) : "f"(v))

#define MMA_TF32(d, a0, a1, a2, a3, b0, b1)                               \
    asm volatile("mma.sync.aligned.m16n8k8.row.col.f32.tf32.tf32.f32 "    \
        "{%0,%1,%2,%3}, {%4,%5,%6,%7}, {%8,%9}, {%0,%1,%2,%3};"           \
        : "+f"(d[0]), "+f"(d[1]), "+f"(d[2]), "+f"(d[3])                  \
        : "r"(a0), "r"(a1), "r"(a2), "r"(a3), "r"(b0), "r"(b1))

__global__ void __launch_bounds__(NTHR, 2)
gating_moe_kernel(const float* __restrict__ x,
                  const float* __restrict__ noise,
                  const float* __restrict__ W,
                  const float* __restrict__ b,
                  float* __restrict__ out)
{
    extern __shared__ float sm[];
    const uint32_t sb = smem_u32(sm);
    const int tid  = threadIdx.x;
    const int wid  = tid >> 5;
    const int l    = tid & 31;
    const int grp  = l >> 2;           // fragment group id (row/col within tile)
    const int pr   = l & 3;            // k-pair id (phys cols 2pr, 2pr+1 via k-perm)
    const int trow = (wid & 3) * 16;   // warp token rows [trow, trow+16)
    const int tile = wid >> 2;         // expert tile: 0 -> e0-7, 1 -> e8-15
    const int tok0 = blockIdx.x * BT;

    // ---- cp.async fill: chunk c -> stage s ----
    auto prefetch = [&](int c, int s) {
        const uint32_t base = sb + (uint32_t)s * STAGE_B;
        #pragma unroll
        for (int k = 0; k < 4; k++) {
            int idx = tid + NTHR * k;          // 1024 float4 of x
            int t  = idx >> 4;
            int dv = idx & 15;
            const float* g = x + (size_t)(tok0 + t) * DIM + c * 64 + dv * 4;
            CP_ASYNC16(base + (uint32_t)((dv >> 1) * 2048 + t * 32 + (dv & 1) * 16), g);
        }
        {
            int e  = tid >> 4;                 // 256 float4 of W
            int dv = tid & 15;
            const float* g = W + (size_t)e * DIM + c * 64 + dv * 4;
            CP_ASYNC16(base + XSTAGE_B + (uint32_t)((dv >> 1) * 512 + e * 32 + (dv & 1) * 16), g);
        }
    };

    float d[4] = {0.f, 0.f, 0.f, 0.f};

    prefetch(0, 0); CP_COMMIT();
    prefetch(1, 1); CP_COMMIT();
    prefetch(2, 2); CP_COMMIT();

    const uint32_t aoff = (uint32_t)((trow + grp) * 32 + pr * 8);          // x row
    const uint32_t boff = (uint32_t)(tile * 256 + grp * 32 + pr * 8);      // W row

    for (int c = 0; c < NCHUNK; c++) {
        if (c < NCHUNK - 2)       { CP_WAIT2(); }
        else if (c == NCHUNK - 2) { CP_WAIT1(); }
        else                      { CP_WAIT0(); }
        __syncthreads();
        if (c + 3 < NCHUNK) { prefetch(c + 3, (c + 3) & 3); CP_COMMIT(); }

        const uint32_t xs = sb + (uint32_t)(c & 3) * STAGE_B;
        const uint32_t ws = xs + XSTAGE_B;

        #pragma unroll
        for (int st = 0; st < 8; st++) {
            float aL0, aL1, aH0, aH1;                  // rows trow+grp / +8
            LDS64(aL0, aL1, xs + (uint32_t)(st * 2048) + aoff);
            LDS64(aH0, aH1, xs + (uint32_t)(st * 2048) + aoff + 256u);
            float b0, b1;
            LDS64(b0, b1, ws + (uint32_t)(st * 512) + boff);

            uint32_t ah0, ah1, ah2, ah3, bh0, bh1;
            CVT_TF32(ah0, aL0); CVT_TF32(ah1, aH0);
            CVT_TF32(ah2, aL1); CVT_TF32(ah3, aH1);
            CVT_TF32(bh0, b0);  CVT_TF32(bh1, b1);
            uint32_t al0 = __float_as_uint(aL0 - __uint_as_float(ah0));
            uint32_t al1 = __float_as_uint(aH0 - __uint_as_float(ah1));
            uint32_t al2 = __float_as_uint(aL1 - __uint_as_float(ah2));
            uint32_t al3 = __float_as_uint(aH1 - __uint_as_float(ah3));
            uint32_t bl0 = __float_as_uint(b0  - __uint_as_float(bh0));
            uint32_t bl1 = __float_as_uint(b1  - __uint_as_float(bh1));

            MMA_TF32(d, ah0, ah1, ah2, ah3, bh0, bh1);
            MMA_TF32(d, ah0, ah1, ah2, ah3, bl0, bl1);
            MMA_TF32(d, al0, al1, al2, al3, bh0, bh1);
        }
    }
    __syncthreads();    // pipeline done; reuse smem base for logits [64][18]

    // ---- scatter accumulators to logits buffer ----
    {
        const int rA = trow + grp;
        const int rB = rA + 8;
        const int cb = tile * 8 + 2 * pr;
        STS64(sb + (uint32_t)(rA * 18 + cb) * 4u, d[0], d[1]);
        STS64(sb + (uint32_t)(rB * 18 + cb) * 4u, d[2], d[3]);
    }
    __syncthreads();

    // ---- epilogue: one token per thread (threads 0..63) ----
    if (tid < BT) {
        const int gtok = tok0 + tid;
        const float4* nz = (const float4*)(noise + (size_t)gtok * NE);
        float4 n0 = nz[0], n1 = nz[1], n2 = nz[2], n3 = nz[3];
        const float4* bb4 = (const float4*)b;
        float4 q0 = bb4[0], q1 = bb4[1], q2 = bb4[2], q3 = bb4[3];

        float nn[16] = {n0.x, n0.y, n0.z, n0.w, n1.x, n1.y, n1.z, n1.w,
                        n2.x, n2.y, n2.z, n2.w, n3.x, n3.y, n3.z, n3.w};
        float bv[16] = {q0.x, q0.y, q0.z, q0.w, q1.x, q1.y, q1.z, q1.w,
                        q2.x, q2.y, q2.z, q2.w, q3.x, q3.y, q3.z, q3.w};

        float v[16];
        #pragma unroll
        for (int e = 0; e < 16; e++) {
            float lg;
            LDS32(lg, sb + (uint32_t)(tid * 18 + e) * 4u);
            v[e] = lg + bv[e] + 0.1f * nn[e];
        }

        // top-2 (stable: earlier index wins ties, matching jax top_k)
        float v1 = -1e30f, v2 = -1e30f;
        int   i1 = -1,     i2 = -1;
        #pragma unroll
        for (int e = 0; e < 16; e++) {
            float val = v[e];
            if (val > v1)      { v2 = v1; i2 = i1; v1 = val; i1 = e; }
            else if (val > v2) { v2 = val; i2 = e; }
        }

        float ew  = expf(v2 - v1);
        float inv = 1.0f / (1.0f + ew);
        float w1  = inv;
        float w2  = ew * inv;

        float o[16];
        #pragma unroll
        for (int e = 0; e < 16; e++)
            o[e] = (e == i1) ? w1 : ((e == i2) ? w2 : 0.0f);

        float4* op = (float4*)(out + (size_t)gtok * NE);
        op[0] = make_float4(o[0],  o[1],  o[2],  o[3]);
        op[1] = make_float4(o[4],  o[5],  o[6],  o[7]);
        op[2] = make_float4(o[8],  o[9],  o[10], o[11]);
        op[3] = make_float4(o[12], o[13], o[14], o[15]);
    }
}

extern "C" void kernel_launch(void* const* d_in, const int* in_sizes, int n_in,
                              void* d_out, int out_size)
{
    const float* x     = (const float*)d_in[0];
    const float* noise = (const float*)d_in[1];
    const float* W     = (const float*)d_in[2];
    const float* b     = (const float*)d_in[3];
    float* out = (float*)d_out;

    cudaFuncSetAttribute(gating_moe_kernel,
                         cudaFuncAttributeMaxDynamicSharedMemorySize, SMEM_BYTES);
    gating_moe_kernel<<<TOK / BT, NTHR, SMEM_BYTES>>>(x, noise, W, b, out);
}

// round 10
// speedup vs baseline: 1.2468x; 1.2468x over previous
#include <cuda_runtime.h>
#include <cstdint>

#define TOK    16384
#define DIM    2048
#define NE     16
#define BT     64
#define NTHR   512
#define KC     256           // K per chunk
#define NCHUNK 8

#define ROWB   1056u         // 1024 B row + 32 B pad (conflict-free LDS64)
#define XS_B   (64u * ROWB)  // 67584
#define STAGE_B (80u * ROWB) // x 64 rows + W 16 rows = 84480
#define MBAR_OFF (2u * STAGE_B)           // 168960
#define SMEM_BYTES (2 * 84480 + 64)       // 169024
#define TX_BYTES 81920u      // real bytes per stage (80 x 1024)

__device__ __forceinline__ uint32_t smem_u32(const void* p) {
    uint32_t a;
    asm("{ .reg .u64 t; cvta.to.shared.u64 t, %1; cvt.u32.u64 %0, t; }" : "=r"(a) : "l"(p));
    return a;
}

#define MBARRIER_INIT(addr, cnt) \
    asm volatile("mbarrier.init.shared.b64 [%0], %1;" :: "r"(addr), "r"(cnt) : "memory")
#define MBARRIER_EXPECT_TX(addr, bytes) \
    asm volatile("mbarrier.arrive.expect_tx.shared.b64 _, [%0], %1;" :: "r"(addr), "r"(bytes) : "memory")
#define MBARRIER_WAIT_PARITY(addr, par) do {                                   \
    uint32_t _m = (addr); uint32_t _p = (par); uint32_t _d;                    \
    asm volatile("{\n\t.reg .pred p;\n\t"                                      \
        "mbarrier.try_wait.parity.acquire.cta.shared::cta.b64 p, [%1], %2;\n\t"\
        "selp.b32 %0, 1, 0, p;\n\t}"                                           \
        : "=r"(_d) : "r"(_m), "r"(_p) : "memory");                             \
    if (!_d) {                                                                 \
        asm volatile("{\n\t.reg .pred P1;\n\t"                                 \
            "WL_%=:\n\t"                                                       \
            "mbarrier.try_wait.parity.acquire.cta.shared::cta.b64 P1, [%0], %1, 0x989680;\n\t" \
            "@P1 bra.uni WD_%=;\n\t"                                           \
            "bra.uni WL_%=;\n\t"                                               \
            "WD_%=:\n\t}" :: "r"(_m), "r"(_p) : "memory");                     \
    }                                                                          \
} while (0)

#define BULK_CP(dst, gsrc, bytes, mbar) \
    asm volatile("cp.async.bulk.shared::cluster.global.mbarrier::complete_tx::bytes [%0], [%1], %2, [%3];" \
        :: "r"(dst), "l"(gsrc), "r"(bytes), "r"(mbar) : "memory")

#define LDS64(a, b, addr) \
    asm volatile("ld.shared.v2.f32 {%0, %1}, [%2];" : "=f"(a), "=f"(b) : "r"(addr))
#define STS64(addr, a, b) \
    asm volatile("st.shared.v2.f32 [%0], {%1, %2};" :: "r"(addr), "f"(a), "f"(b))
#define LDS32(v, addr) asm volatile("ld.shared.f32 %0, [%1];" : "=f"(v) : "r"(addr))
#define CVT_TF32(h, v) asm("cvt.rna.tf32.f32 %0, %1;" : "=r"(h) : "f"(v))

#define MMA_TF32(d, a0, a1, a2, a3, b0, b1)                               \
    asm volatile("mma.sync.aligned.m16n8k8.row.col.f32.tf32.tf32.f32 "    \
        "{%0,%1,%2,%3}, {%4,%5,%6,%7}, {%8,%9}, {%0,%1,%2,%3};"           \
        : "+f"(d[0]), "+f"(d[1]), "+f"(d[2]), "+f"(d[3])                  \
        : "r"(a0), "r"(a1), "r"(a2), "r"(a3), "r"(b0), "r"(b1))

__global__ void __launch_bounds__(NTHR, 1)
gating_moe_kernel(const float* __restrict__ x,
                  const float* __restrict__ noise,
                  const float* __restrict__ W,
                  const float* __restrict__ b,
                  float* __restrict__ out)
{
    extern __shared__ float sm[];
    const uint32_t sb = smem_u32(sm);
    const int tid   = threadIdx.x;
    const int wid   = tid >> 5;
    const int l     = tid & 31;
    const int grp   = l >> 2;            // fragment group (row/col)
    const int pr    = l & 3;             // k-pair (phys k = 2pr, 2pr+1 via k-perm)
    const int trow  = (wid & 3) * 16;    // token rows [trow, trow+16)
    const int tile  = (wid >> 2) & 1;    // expert tile 0: e0-7, 1: e8-15
    const int khalf = wid >> 3;          // k-half: st 0-15 / 16-31
    const int tok0  = blockIdx.x * BT;

    // ---- mbarrier init ----
    if (tid == 0) {
        MBARRIER_INIT(sb + MBAR_OFF + 0u, 1);
        MBARRIER_INIT(sb + MBAR_OFF + 8u, 1);
    }
    __syncthreads();

    // ---- fill chunk c into stage s: 80 bulk copies of 1 KB ----
    auto prefetch = [&](int c, int s) {
        const uint32_t mb   = sb + MBAR_OFF + 8u * (uint32_t)s;
        const uint32_t base = sb + (uint32_t)s * STAGE_B;
        if (tid == 0) MBARRIER_EXPECT_TX(mb, TX_BYTES);
        if (tid < 64) {
            const char* g = (const char*)(x + (size_t)(tok0 + tid) * DIM + c * KC);
            BULK_CP(base + (uint32_t)tid * ROWB, g, 1024u, mb);
        } else if (tid < 80) {
            const int e = tid - 64;
            const char* g = (const char*)(W + (size_t)e * DIM + c * KC);
            BULK_CP(base + XS_B + (uint32_t)e * ROWB, g, 1024u, mb);
        }
    };

    prefetch(0, 0);
    prefetch(1, 1);

    float d[4] = {0.f, 0.f, 0.f, 0.f};

    // per-thread LDS bases (within a stage)
    const uint32_t aoff = (uint32_t)(trow + grp) * ROWB + (uint32_t)(khalf * 16 * 32 + pr * 8);
    const uint32_t boff = XS_B + (uint32_t)(tile * 8 + grp) * ROWB
                        + (uint32_t)(khalf * 16 * 32 + pr * 8);

    for (int c = 0; c < NCHUNK; c++) {
        MBARRIER_WAIT_PARITY(sb + MBAR_OFF + 8u * (uint32_t)(c & 1), (uint32_t)((c >> 1) & 1));

        const uint32_t xs = sb + (uint32_t)(c & 1) * STAGE_B;

        #pragma unroll
        for (int j = 0; j < 16; j++) {
            const uint32_t ko = (uint32_t)(j * 32);
            float aL0, aL1, aH0, aH1, b0, b1;
            LDS64(aL0, aL1, xs + aoff + ko);            // row trow+grp
            LDS64(aH0, aH1, xs + aoff + ko + 8u * ROWB);// row trow+grp+8
            LDS64(b0,  b1,  xs + boff + ko);            // expert tile*8+grp

            uint32_t ah0, ah1, ah2, ah3, bh0, bh1;
            CVT_TF32(ah0, aL0); CVT_TF32(ah1, aH0);
            CVT_TF32(ah2, aL1); CVT_TF32(ah3, aH1);
            CVT_TF32(bh0, b0);  CVT_TF32(bh1, b1);
            uint32_t al0 = __float_as_uint(aL0 - __uint_as_float(ah0));
            uint32_t al1 = __float_as_uint(aH0 - __uint_as_float(ah1));
            uint32_t al2 = __float_as_uint(aL1 - __uint_as_float(ah2));
            uint32_t al3 = __float_as_uint(aH1 - __uint_as_float(ah3));
            uint32_t bl0 = __float_as_uint(b0  - __uint_as_float(bh0));
            uint32_t bl1 = __float_as_uint(b1  - __uint_as_float(bh1));

            MMA_TF32(d, ah0, ah1, ah2, ah3, bh0, bh1);
            MMA_TF32(d, ah0, ah1, ah2, ah3, bl0, bl1);
            MMA_TF32(d, al0, al1, al2, al3, bh0, bh1);
        }

        __syncthreads();                      // stage (c&1) fully consumed
        if (c + 2 < NCHUNK) prefetch(c + 2, c & 1);
    }

    // ---- k-half partials -> smem (reuse stage 0), [64][18] per half ----
    {
        const uint32_t buf = sb + (uint32_t)(khalf * 4608);
        const int rA = trow + grp;
        const int rB = rA + 8;
        const int cb = tile * 8 + 2 * pr;
        STS64(buf + (uint32_t)(rA * 18 + cb) * 4u, d[0], d[1]);
        STS64(buf + (uint32_t)(rB * 18 + cb) * 4u, d[2], d[3]);
    }
    __syncthreads();

    // ---- epilogue: one token per thread (threads 0..63) ----
    if (tid < BT) {
        const int gtok = tok0 + tid;
        const float4* nz = (const float4*)(noise + (size_t)gtok * NE);
        float4 n0 = nz[0], n1 = nz[1], n2 = nz[2], n3 = nz[3];
        const float4* bb4 = (const float4*)b;
        float4 q0 = bb4[0], q1 = bb4[1], q2 = bb4[2], q3 = bb4[3];

        float nn[16] = {n0.x, n0.y, n0.z, n0.w, n1.x, n1.y, n1.z, n1.w,
                        n2.x, n2.y, n2.z, n2.w, n3.x, n3.y, n3.z, n3.w};
        float bv[16] = {q0.x, q0.y, q0.z, q0.w, q1.x, q1.y, q1.z, q1.w,
                        q2.x, q2.y, q2.z, q2.w, q3.x, q3.y, q3.z, q3.w};

        float v[16];
        #pragma unroll
        for (int e = 0; e < 16; e++) {
            float l0, l1;
            LDS32(l0, sb + (uint32_t)(tid * 18 + e) * 4u);
            LDS32(l1, sb + 4608u + (uint32_t)(tid * 18 + e) * 4u);
            v[e] = (l0 + l1) + bv[e] + 0.1f * nn[e];
        }

        // top-2 (stable: earlier index wins ties, matching jax top_k)
        float v1 = -1e30f, v2 = -1e30f;
        int   i1 = -1,     i2 = -1;
        #pragma unroll
        for (int e = 0; e < 16; e++) {
            float val = v[e];
            if (val > v1)      { v2 = v1; i2 = i1; v1 = val; i1 = e; }
            else if (val > v2) { v2 = val; i2 = e; }
        }

        float ew  = expf(v2 - v1);
        float inv = 1.0f / (1.0f + ew);
        float w1  = inv;
        float w2  = ew * inv;

        float o[16];
        #pragma unroll
        for (int e = 0; e < 16; e++)
            o[e] = (e == i1) ? w1 : ((e == i2) ? w2 : 0.0f);

        float4* op = (float4*)(out + (size_t)gtok * NE);
        op[0] = make_float4(o[0],  o[1],  o[2],  o[3]);
        op[1] = make_float4(o[4],  o[5],  o[6],  o[7]);
        op[2] = make_float4(o[8],  o[9],  o[10], o[11]);
        op[3] = make_float4(o[12], o[13], o[14], o[15]);
    }
}

extern "C" void kernel_launch(void* const* d_in, const int* in_sizes, int n_in,
                              void* d_out, int out_size)
{
    const float* x     = (const float*)d_in[0];
    const float* noise = (const float*)d_in[1];
    const float* W     = (const float*)d_in[2];
    const float* b     = (const float*)d_in[3];
    float* out = (float*)d_out;

    cudaFuncSetAttribute(gating_moe_kernel,
                         cudaFuncAttributeMaxDynamicSharedMemorySize, SMEM_BYTES);
    gating_moe_kernel<<<TOK / BT, NTHR, SMEM_BYTES>>>(x, noise, W, b, out);
}